// round 12
// baseline (speedup 1.0000x reference)
#include <cuda_runtime.h>
#include <cuda_bf16.h>
#include <cuda_fp16.h>
#include <math.h>
#include <stdint.h>

// ===========================================================================
// FNet block on GB300 (compute_103 PTX -> mma.sync HMMA path)
//   ft  = Re(FFT_seq(D * reverse_hidden(x)))   [FFT_D^2 = D * index reversal]
//   t   = LayerNorm(x + ft)*g + b   -> fp16
//   h   = GELU(t @ w1 + b1)         -> 1-term fp16 mma GEMM -> fp16
//   out = (h @ w2 + b2) * mask      -> 1-term fp16 mma GEMM -> fp32
// FFT: register-resident radix-16/16/8 (2 smem transposes instead of 6 rounds)
// ===========================================================================

#define B_ 8
#define S_ 2048
#define D_ 1024
#define ROWS (B_ * S_)
#define ELEMS ((long)ROWS * D_)

__device__ __align__(256) float   g_ft[ELEMS];
__device__ __align__(256) __half  g_t[ELEMS];
__device__ __align__(256) __half  g_h[ELEMS];
__device__ __align__(256) __half  g_w1h[D_ * D_];
__device__ __align__(256) __half  g_w2h[D_ * D_];
__device__ __align__(256) float2  g_tw[1024];

// ------------------------- helpers ----------------------------------------
__device__ __forceinline__ uint32_t smem_u32(const void* p) {
    uint32_t a;
    asm("{ .reg .u64 t; cvta.to.shared.u64 t, %1; cvt.u32.u64 %0, t; }"
        : "=r"(a) : "l"(p));
    return a;
}
__device__ __forceinline__ void cp16(uint32_t s, const void* g) {
    asm volatile("cp.async.cg.shared.global [%0], [%1], 16;" :: "r"(s), "l"(g));
}
#define CP_COMMIT() asm volatile("cp.async.commit_group;" ::: "memory")
#define CP_WAIT(n)  asm volatile("cp.async.wait_group %0;" :: "n"(n) : "memory")

__device__ __forceinline__ void ldsm_x4(uint32_t* r, uint32_t addr) {
    asm volatile("ldmatrix.sync.aligned.m8n8.x4.shared.b16 {%0,%1,%2,%3}, [%4];"
                 : "=r"(r[0]), "=r"(r[1]), "=r"(r[2]), "=r"(r[3]) : "r"(addr));
}
__device__ __forceinline__ void mma_f16(float* c, const uint32_t* a, const uint32_t* b) {
    asm volatile("mma.sync.aligned.m16n8k16.row.col.f32.f16.f16.f32 "
                 "{%0,%1,%2,%3}, {%4,%5,%6,%7}, {%8,%9}, {%0,%1,%2,%3};"
                 : "+f"(c[0]), "+f"(c[1]), "+f"(c[2]), "+f"(c[3])
                 : "r"(a[0]), "r"(a[1]), "r"(a[2]), "r"(a[3]),
                   "r"(b[0]), "r"(b[1]));
}
__device__ __forceinline__ float2 cmul(float2 a, float2 b) {
    return make_float2(a.x * b.x - a.y * b.y, a.x * b.y + a.y * b.x);
}
__device__ __forceinline__ float2 cadd(float2 a, float2 b) {
    return make_float2(a.x + b.x, a.y + b.y);
}
__device__ __forceinline__ float2 csub(float2 a, float2 b) {
    return make_float2(a.x - b.x, a.y - b.y);
}

// padded smem index (float2 units): <=2-way conflicts on all access patterns
__device__ __forceinline__ int aidx(int e, int q) {
    return e * 4 + q + (e >> 4) + 2 * (e >> 8);
}
#define FFT_SMEM_F2 8336
#define FFT_SMEM_BYTES (FFT_SMEM_F2 * 8)   // 66688

// ===========================================================================
// Kernel 0a: twiddle table  tw[t] = exp(-i*pi*t/1024)
// ===========================================================================
__global__ void twinit_kernel(float2* __restrict__ tw) {
    int t = blockIdx.x * 256 + threadIdx.x;
    float s, c;
    sincospif(-(float)t / 1024.0f, &s, &c);
    tw[t] = make_float2(c, s);
}

// ===========================================================================
// Kernel 0b: weight transpose + fp16 convert.  w[K][N] -> wt[N][K] fp16
// ===========================================================================
__global__ __launch_bounds__(256) void wsplit_kernel(
    const float* __restrict__ w, __half* __restrict__ wh)
{
    __shared__ float tile[32][33];
    const int bx = blockIdx.x * 32;
    const int by = blockIdx.y * 32;
    const int tx = threadIdx.x, ty = threadIdx.y;
    for (int i = ty; i < 32; i += 8)
        tile[i][tx] = w[(long)(by + i) * D_ + bx + tx];
    __syncthreads();
    for (int i = ty; i < 32; i += 8) {
        int n = bx + i;
        int k = by + tx;
        wh[(long)n * D_ + k] = __float2half(tile[tx][i]);
    }
}

// ===========================================================================
// Kernel 1: real-packed FFT along seq, register-resident.
// 8 real cols -> 4 complex FFTs of 2048. 512 threads: q = tid>>7 (column),
// t = tid&127, 16 complex elements per thread.
//   round 1: e = 16t+r          stages h=1..8    (radix-16, const twiddles)
//   round 2: e = tl+16rl+256th  stages h=16..128 (radix-16)
//   round 3: e = u+256r3        stages h=256..1024 (radix-8 x2, u=2t,2t+1)
// then unpack Re, scatter reversed hidden index, scale D.
// ===========================================================================
__global__ __launch_bounds__(512) void fftr_kernel(
    const float* __restrict__ x, float* __restrict__ ft,
    const float2* __restrict__ tw)
{
    extern __shared__ float2 sa[];
    const int c0  = blockIdx.x * 8;
    const int b   = blockIdx.y;
    const int tid = threadIdx.x;
    const int q   = tid >> 7;
    const int t   = tid & 127;

    float2 v[16];

    // ---- load (bit-reversed storage): e = 16t + r, value = x[brev(e)]
    const float* xp = x + (long)b * S_ * D_ + c0 + 2 * q;
    #pragma unroll
    for (int r = 0; r < 16; r++) {
        int e   = 16 * t + r;
        int row = __brev(e) >> 21;
        v[r] = *(const float2*)(xp + (long)row * D_);
    }

    // ---- round 1: stages h=1,2,4,8 (constant twiddles e^{-i pi k/8})
    {
        const float2 T[8] = {
            { 1.0f, 0.0f },
            { 0.9238795325112867f, -0.3826834323650898f },
            { 0.7071067811865476f, -0.7071067811865476f },
            { 0.3826834323650898f, -0.9238795325112867f },
            { 0.0f, -1.0f },
            { -0.3826834323650898f, -0.9238795325112867f },
            { -0.7071067811865476f, -0.7071067811865476f },
            { -0.9238795325112867f, -0.3826834323650898f } };
        #pragma unroll
        for (int H = 1; H <= 8; H <<= 1) {
            #pragma unroll
            for (int r = 0; r < 16; r++) {
                if (!(r & H)) {
                    float2 w  = T[(r & (H - 1)) * (8 / H)];
                    float2 tt = cmul(w, v[r + H]);
                    float2 u  = v[r];
                    v[r]     = cadd(u, tt);
                    v[r + H] = csub(u, tt);
                }
            }
        }
    }

    // ---- transpose 1: store e=16t+r, load e=tl+16rl+256th
    #pragma unroll
    for (int r = 0; r < 16; r++)
        sa[aidx(16 * t + r, q)] = v[r];
    __syncthreads();

    const int tl = t & 15, th = t >> 4;
    #pragma unroll
    for (int rl = 0; rl < 16; rl++)
        v[rl] = sa[aidx(tl + 16 * rl + 256 * th, q)];

    // ---- round 2: stages h=16H, H=1,2,4,8;  j = tl + 16*(rl&(H-1))
    #pragma unroll
    for (int H = 1; H <= 8; H <<= 1) {
        const int step = 64 / H;
        #pragma unroll
        for (int rl = 0; rl < 16; rl++) {
            if (!(rl & H)) {
                float2 w  = tw[(tl + 16 * (rl & (H - 1))) * step];
                float2 tt = cmul(w, v[rl + H]);
                float2 u  = v[rl];
                v[rl]     = cadd(u, tt);
                v[rl + H] = csub(u, tt);
            }
        }
    }

    // ---- transpose 2: store back same map, load e = u + 256*r3 (u=2t+du)
    __syncthreads();
    #pragma unroll
    for (int rl = 0; rl < 16; rl++)
        sa[aidx(tl + 16 * rl + 256 * th, q)] = v[rl];
    __syncthreads();

    #pragma unroll
    for (int du = 0; du < 2; du++)
        #pragma unroll
        for (int r3 = 0; r3 < 8; r3++)
            v[du * 8 + r3] = sa[aidx((2 * t + du) + 256 * r3, q)];

    // ---- round 3: stages h=256H3, H3=1,2,4;  j = u + 256*(r3&(H3-1))
    #pragma unroll
    for (int H = 1; H <= 4; H <<= 1) {
        const int step = 4 / H;
        #pragma unroll
        for (int du = 0; du < 2; du++) {
            const int u0 = 2 * t + du;
            #pragma unroll
            for (int r3 = 0; r3 < 8; r3++) {
                if (!(r3 & H)) {
                    float2 w  = tw[(u0 + 256 * (r3 & (H - 1))) * step];
                    float2 tt = cmul(w, v[du * 8 + r3 + H]);
                    float2 u  = v[du * 8 + r3];
                    v[du * 8 + r3]     = cadd(u, tt);
                    v[du * 8 + r3 + H] = csub(u, tt);
                }
            }
        }
    }

    // ---- final store (natural order) + unpack
    __syncthreads();
    #pragma unroll
    for (int du = 0; du < 2; du++)
        #pragma unroll
        for (int r3 = 0; r3 < 8; r3++)
            sa[aidx((2 * t + du) + 256 * r3, q)] = v[du * 8 + r3];
    __syncthreads();

    float* fp = ft + (long)b * S_ * D_;
    for (int i = tid; i < S_ * 8; i += 512) {
        int s   = i >> 3;
        int col = i & 7;
        int qq  = col >> 1;
        int ns  = (S_ - s) & (S_ - 1);
        float2 zs = sa[aidx(s, qq)];
        float2 zn = sa[aidx(ns, qq)];
        float val = (col & 1) ? (zs.y + zn.y) : (zs.x + zn.x);
        val *= 512.0f;                          // D * 0.5
        int dout = (D_ - (c0 + col)) & (D_ - 1);
        fp[(long)s * D_ + dout] = val;
    }
}

// ===========================================================================
// Kernel 2: t = LN(x + ft)*g + b  -> fp16  (float4 I/O)
// ===========================================================================
__device__ __forceinline__ float block_sum_256(float val, float* sh) {
    #pragma unroll
    for (int o = 16; o > 0; o >>= 1) val += __shfl_xor_sync(0xFFFFFFFFu, val, o);
    int lane = threadIdx.x & 31, w = threadIdx.x >> 5;
    if (lane == 0) sh[w] = val;
    __syncthreads();
    if (w == 0) {
        float v = (lane < 8) ? sh[lane] : 0.0f;
        #pragma unroll
        for (int o = 4; o > 0; o >>= 1) v += __shfl_xor_sync(0xFFFFFFFFu, v, o);
        if (lane == 0) sh[0] = v;
    }
    __syncthreads();
    float r = sh[0];
    __syncthreads();
    return r;
}

__global__ __launch_bounds__(256) void add_ln_kernel(
    const float* __restrict__ x, const float* __restrict__ ft,
    const float* __restrict__ gamma, const float* __restrict__ beta,
    __half* __restrict__ t_out)
{
    __shared__ float sh[8];
    const int row = blockIdx.x;
    const int tid = threadIdx.x;
    const long base = (long)row * D_ + tid * 4;

    float4 xv = *(const float4*)(x + base);
    float4 fv = *(const float4*)(ft + base);
    float v0 = xv.x + fv.x, v1 = xv.y + fv.y, v2 = xv.z + fv.z, v3 = xv.w + fv.w;

    float mu = block_sum_256(v0 + v1 + v2 + v3, sh) * (1.0f / D_);
    float d0 = v0 - mu, d1 = v1 - mu, d2 = v2 - mu, d3 = v3 - mu;
    float var = block_sum_256(d0 * d0 + d1 * d1 + d2 * d2 + d3 * d3, sh) * (1.0f / D_);
    float rs  = rsqrtf(var + 1e-5f);

    float4 gv = *(const float4*)(gamma + tid * 4);
    float4 bv = *(const float4*)(beta + tid * 4);
    float r0 = d0 * rs * gv.x + bv.x;
    float r1 = d1 * rs * gv.y + bv.y;
    float r2 = d2 * rs * gv.z + bv.z;
    float r3 = d3 * rs * gv.w + bv.w;

    __half2 h01 = __floats2half2_rn(r0, r1);
    __half2 h23 = __floats2half2_rn(r2, r3);
    uint2 pk = make_uint2(*(uint32_t*)&h01, *(uint32_t*)&h23);
    *(uint2*)(t_out + base) = pk;
}

// ===========================================================================
// Kernel 3/4: 1-term fp16 GEMM via mma.sync. Tile 128M x 128N x 32K,
// 128 threads (4 warps, 2x2 grid, warp tile 64x64), cp.async double buffer.
// fuse 0: bias+GELU -> fp16.   fuse 1: bias, *mask -> fp32.   [R10-proven]
// ===========================================================================
#define BK 32
#define ROWB 80                        // 64B data + 16B pad
#define TILE_R_B (128 * ROWB)          // 10240 per 128-row tile
#define OFF_A 0
#define OFF_BW TILE_R_B
#define STAGE_B (2 * TILE_R_B)              // 20480
#define GEMM_SMEM (2 * STAGE_B)             // 40960

__global__ __launch_bounds__(128) void gemm_mma_kernel(
    const __half* __restrict__ A, const __half* __restrict__ Bw,
    const float* __restrict__ bias, const float* __restrict__ mask,
    __half* __restrict__ Ch, float* __restrict__ Cf, int fuse)
{
    extern __shared__ char sm[];
    const uint32_t sb  = smem_u32(sm);
    const int tid  = threadIdx.x;
    const int wid  = tid >> 5;
    const int lane = tid & 31;
    const int bm = blockIdx.y * 128;
    const int bn = blockIdx.x * 128;
    const int warp_m = wid & 1;        // 64-row slab
    const int warp_n = wid >> 1;       // 64-col slab

    auto load_stage = [&](int stage, int k0) {
        const uint32_t st = sb + stage * STAGE_B;
        #pragma unroll
        for (int t = 0; t < 4; t++) {   // A: 512 chunks, 4 per thread
            int idx = tid + t * 128;
            int row = idx >> 2, ch = idx & 3;
            uint32_t so = row * ROWB + ch * 16;
            long ga = (long)(bm + row) * D_ + k0 + ch * 8;
            cp16(st + OFF_A + so, A + ga);
        }
        #pragma unroll
        for (int t = 0; t < 4; t++) {   // W: 512 chunks, 4 per thread
            int idx = tid + t * 128;
            int row = idx >> 2, ch = idx & 3;
            uint32_t so = row * ROWB + ch * 16;
            long gb = (long)(bn + row) * D_ + k0 + ch * 8;
            cp16(st + OFF_BW + so, Bw + gb);
        }
    };

    float acc[4][8][4];
    #pragma unroll
    for (int m = 0; m < 4; m++)
        #pragma unroll
        for (int n = 0; n < 8; n++)
            #pragma unroll
            for (int q = 0; q < 4; q++) acc[m][n][q] = 0.0f;

    load_stage(0, 0);
    CP_COMMIT();

    const int a_lrow = lane & 15;
    const int a_kch  = lane >> 4;
    const int b_lrow = ((lane >> 4) & 1) * 8 + (lane & 7);
    const int b_kch  = (lane >> 3) & 1;

    const int NIT = D_ / BK;   // 32
    for (int it = 0; it < NIT; it++) {
        const int s = it & 1;
        if (it + 1 < NIT) {
            load_stage(s ^ 1, (it + 1) * BK);
            CP_COMMIT();
            CP_WAIT(1);
        } else {
            CP_WAIT(0);
        }
        __syncthreads();

        const uint32_t tA  = sb + s * STAGE_B + OFF_A;
        const uint32_t tBw = sb + s * STAGE_B + OFF_BW;

        #pragma unroll
        for (int ks = 0; ks < 2; ks++) {
            const int kb = ks * 32;
            uint32_t ah[4][4];
            #pragma unroll
            for (int m = 0; m < 4; m++) {
                uint32_t off = (uint32_t)((warp_m * 64 + m * 16 + a_lrow) * ROWB
                                          + kb + a_kch * 16);
                ldsm_x4(ah[m], tA + off);
            }
            #pragma unroll
            for (int p = 0; p < 4; p++) {
                uint32_t off = (uint32_t)((warp_n * 64 + p * 16 + b_lrow) * ROWB
                                          + kb + b_kch * 16);
                uint32_t rh[4];
                ldsm_x4(rh, tBw + off);
                #pragma unroll
                for (int m = 0; m < 4; m++) {
                    mma_f16(acc[m][2 * p],     ah[m], rh);
                    mma_f16(acc[m][2 * p + 1], ah[m], rh + 2);
                }
            }
        }
        __syncthreads();
    }

    // ------------------------------ epilogue -------------------------------
    const int g  = lane >> 2;
    const int t2 = (lane & 3) * 2;
    #pragma unroll
    for (int m = 0; m < 4; m++) {
        const int row0 = bm + warp_m * 64 + m * 16 + g;
        #pragma unroll
        for (int half = 0; half < 2; half++) {
            const int row = row0 + half * 8;
            const float mk = (fuse == 1) ? mask[row] : 0.0f;
            #pragma unroll
            for (int n = 0; n < 8; n++) {
                const int col = bn + warp_n * 64 + n * 8 + t2;
                float v0 = acc[m][n][2 * half]     + bias[col];
                float v1 = acc[m][n][2 * half + 1] + bias[col + 1];
                if (fuse == 0) {
                    v0 = 0.5f * v0 * (1.0f + erff(v0 * 0.70710678118654752f));
                    v1 = 0.5f * v1 * (1.0f + erff(v1 * 0.70710678118654752f));
                    __half h0 = __float2half(v0);
                    __half h1 = __float2half(v1);
                    uint32_t hp = ((uint32_t)__half_as_ushort(h1) << 16)
                                | __half_as_ushort(h0);
                    *(uint32_t*)(Ch + (long)row * D_ + col) = hp;
                } else {
                    float2 o = make_float2(v0 * mk, v1 * mk);
                    *(float2*)(Cf + (long)row * D_ + col) = o;
                }
            }
        }
    }
}

// ===========================================================================
// Launch
// ===========================================================================
extern "C" void kernel_launch(void* const* d_in, const int* in_sizes, int n_in,
                              void* d_out, int out_size)
{
    const float* x    = (const float*)d_in[0];
    const float* mask = (const float*)d_in[1];
    const float* ln_g = (const float*)d_in[2];
    const float* ln_b = (const float*)d_in[3];
    const float* w1   = (const float*)d_in[4];
    const float* b1   = (const float*)d_in[5];
    const float* w2   = (const float*)d_in[6];
    const float* b2   = (const float*)d_in[7];
    float* out = (float*)d_out;

    float *ft; float2 *tw;
    __half *t, *h, *w1h, *w2h;
    cudaGetSymbolAddress((void**)&ft,  g_ft);
    cudaGetSymbolAddress((void**)&tw,  g_tw);
    cudaGetSymbolAddress((void**)&t,   g_t);
    cudaGetSymbolAddress((void**)&h,   g_h);
    cudaGetSymbolAddress((void**)&w1h, g_w1h);
    cudaGetSymbolAddress((void**)&w2h, g_w2h);

    cudaFuncSetAttribute(fftr_kernel, cudaFuncAttributeMaxDynamicSharedMemorySize, FFT_SMEM_BYTES);
    cudaFuncSetAttribute(gemm_mma_kernel, cudaFuncAttributeMaxDynamicSharedMemorySize, GEMM_SMEM);

    twinit_kernel<<<4, 256>>>(tw);
    wsplit_kernel<<<dim3(32, 32), dim3(32, 8)>>>(w1, w1h);
    wsplit_kernel<<<dim3(32, 32), dim3(32, 8)>>>(w2, w2h);
    fftr_kernel<<<dim3(D_ / 8, B_), 512, FFT_SMEM_BYTES>>>(x, ft, tw);
    add_ln_kernel<<<ROWS, 256>>>(x, ft, ln_g, ln_b, t);
    gemm_mma_kernel<<<dim3(D_ / 128, ROWS / 128), 128, GEMM_SMEM>>>(
        t, w1h, b1, nullptr, h, nullptr, 0);
    gemm_mma_kernel<<<dim3(D_ / 128, ROWS / 128), 128, GEMM_SMEM>>>(
        h, w2h, b2, mask, nullptr, out, 1);
}

// round 13
// speedup vs baseline: 1.0225x; 1.0225x over previous
#include <cuda_runtime.h>
#include <cuda_bf16.h>
#include <cuda_fp16.h>
#include <math.h>
#include <stdint.h>

// ===========================================================================
// FNet block on GB300 (compute_103 PTX -> mma.sync HMMA path)
//   sum = x + Re(FFT_seq(D * reverse_hidden(x)))  [fused in fftc]
//   t   = LayerNorm(sum)*g + b   -> fp16
//   h   = GELU(t @ w1 + b1)      -> 1-term fp16 mma GEMM -> fp16
//   out = (h @ w2 + b2) * mask   -> 1-term fp16 mma GEMM -> fp32
// ===========================================================================

#define B_ 8
#define S_ 2048
#define D_ 1024
#define ROWS (B_ * S_)
#define ELEMS ((long)ROWS * D_)

__device__ __align__(256) float   g_sum[ELEMS];
__device__ __align__(256) __half  g_t[ELEMS];
__device__ __align__(256) __half  g_h[ELEMS];
__device__ __align__(256) __half  g_w1h[D_ * D_];
__device__ __align__(256) __half  g_w2h[D_ * D_];
__device__ __align__(256) float2  g_tw[1024];

// ------------------------- helpers ----------------------------------------
__device__ __forceinline__ uint32_t smem_u32(const void* p) {
    uint32_t a;
    asm("{ .reg .u64 t; cvta.to.shared.u64 t, %1; cvt.u32.u64 %0, t; }"
        : "=r"(a) : "l"(p));
    return a;
}
__device__ __forceinline__ void cp16(uint32_t s, const void* g) {
    asm volatile("cp.async.cg.shared.global [%0], [%1], 16;" :: "r"(s), "l"(g));
}
#define CP_COMMIT() asm volatile("cp.async.commit_group;" ::: "memory")
#define CP_WAIT(n)  asm volatile("cp.async.wait_group %0;" :: "n"(n) : "memory")

__device__ __forceinline__ void ldsm_x4(uint32_t* r, uint32_t addr) {
    asm volatile("ldmatrix.sync.aligned.m8n8.x4.shared.b16 {%0,%1,%2,%3}, [%4];"
                 : "=r"(r[0]), "=r"(r[1]), "=r"(r[2]), "=r"(r[3]) : "r"(addr));
}
__device__ __forceinline__ void mma_f16(float* c, const uint32_t* a, const uint32_t* b) {
    asm volatile("mma.sync.aligned.m16n8k16.row.col.f32.f16.f16.f32 "
                 "{%0,%1,%2,%3}, {%4,%5,%6,%7}, {%8,%9}, {%0,%1,%2,%3};"
                 : "+f"(c[0]), "+f"(c[1]), "+f"(c[2]), "+f"(c[3])
                 : "r"(a[0]), "r"(a[1]), "r"(a[2]), "r"(a[3]),
                   "r"(b[0]), "r"(b[1]));
}
__device__ __forceinline__ float2 cmul(float2 a, float2 b) {
    return make_float2(a.x * b.x - a.y * b.y, a.x * b.y + a.y * b.x);
}

// padded smem index for the FFT working set (in float2 units)  [R11-proven]
__device__ __forceinline__ int sidx(int e, int q) {
    return e * 4 + q + 2 * (e >> 2) + 2 * (e >> 6);
}
#define FFT_SMEM_F2 9276
#define FFT_SMEM_BYTES (FFT_SMEM_F2 * 8)   // 74208

// ===========================================================================
// Kernel 0a: twiddle table  tw[t] = exp(-i*pi*t/1024)
// ===========================================================================
__global__ void twinit_kernel(float2* __restrict__ tw) {
    int t = blockIdx.x * 256 + threadIdx.x;
    float s, c;
    sincospif(-(float)t / 1024.0f, &s, &c);
    tw[t] = make_float2(c, s);
}

// ===========================================================================
// Kernel 0b: weight transpose + fp16 convert, both weights in one launch.
// z=0: w1 -> w1h ; z=1: w2 -> w2h.     w[K][N] -> wt[N][K] fp16
// ===========================================================================
__global__ __launch_bounds__(256) void wsplit_kernel(
    const float* __restrict__ w1, __half* __restrict__ w1h,
    const float* __restrict__ w2, __half* __restrict__ w2h)
{
    const float* w  = blockIdx.z ? w2 : w1;
    __half* wh      = blockIdx.z ? w2h : w1h;
    __shared__ float tile[32][33];
    const int bx = blockIdx.x * 32;
    const int by = blockIdx.y * 32;
    const int tx = threadIdx.x, ty = threadIdx.y;
    for (int i = ty; i < 32; i += 8)
        tile[i][tx] = w[(long)(by + i) * D_ + bx + tx];
    __syncthreads();
    for (int i = ty; i < 32; i += 8) {
        int n = bx + i;
        int k = by + tx;
        wh[(long)n * D_ + k] = __float2half(tile[tx][i]);
    }
}

// ===========================================================================
// Kernel 1: real-packed FFT along seq (8 real cols -> 4 complex FFTs),
// fused radix-4 rounds (h=1,4,16,64,256) + final radix-2 (h=1024).
// Padded smem indexing. Output fused with residual: sum = x + ft.
// ===========================================================================
__global__ __launch_bounds__(512) void fftc_kernel(
    const float* __restrict__ x, float* __restrict__ sum,
    const float2* __restrict__ tw)
{
    extern __shared__ float2 sa[];   // FFT_SMEM_F2 float2
    const int c0  = blockIdx.x * 8;
    const int b   = blockIdx.y;
    const int tid = threadIdx.x;

    const float* xp = x + (long)b * S_ * D_ + c0;
    for (int r = tid; r < S_; r += 512) {
        int br = __brev(r) >> 21;
        float4 v0 = *(const float4*)(xp + (long)r * D_);
        float4 v1 = *(const float4*)(xp + (long)r * D_ + 4);
        float2* d = sa + sidx(br, 0);     // q=0..3 contiguous
        d[0] = make_float2(v0.x, v0.y);
        d[1] = make_float2(v0.z, v0.w);
        d[2] = make_float2(v1.x, v1.y);
        d[3] = make_float2(v1.z, v1.w);
    }
    __syncthreads();

    #pragma unroll
    for (int h = 1; h <= 256; h *= 4) {
        const int step1 = 1024 / h;
        const int step2 = 512 / h;
        #pragma unroll
        for (int t = 0; t < 4; t++) {
            int i = tid + t * 512;
            int q = i & 3;
            int g = i >> 2;
            int j = g & (h - 1);
            int i0 = ((g - j) << 2) + j;
            float2 u0 = sa[sidx(i0, q)];
            float2 u1 = sa[sidx(i0 + h, q)];
            float2 u2 = sa[sidx(i0 + 2 * h, q)];
            float2 u3 = sa[sidx(i0 + 3 * h, q)];
            float2 w1 = tw[j * step1];
            float2 wA = tw[j * step2];
            float2 wB = make_float2(wA.y, -wA.x);
            float2 t1 = cmul(w1, u1);
            float2 a0 = make_float2(u0.x + t1.x, u0.y + t1.y);
            float2 a1 = make_float2(u0.x - t1.x, u0.y - t1.y);
            float2 t3 = cmul(w1, u3);
            float2 a2 = make_float2(u2.x + t3.x, u2.y + t3.y);
            float2 a3 = make_float2(u2.x - t3.x, u2.y - t3.y);
            float2 t2 = cmul(wA, a2);
            float2 tB = cmul(wB, a3);
            sa[sidx(i0, q)]         = make_float2(a0.x + t2.x, a0.y + t2.y);
            sa[sidx(i0 + h, q)]     = make_float2(a1.x + tB.x, a1.y + tB.y);
            sa[sidx(i0 + 2 * h, q)] = make_float2(a0.x - t2.x, a0.y - t2.y);
            sa[sidx(i0 + 3 * h, q)] = make_float2(a1.x - tB.x, a1.y - tB.y);
        }
        __syncthreads();
    }

    #pragma unroll
    for (int t = 0; t < 8; t++) {
        int i = tid + t * 512;
        int q = i & 3;
        int p = i >> 2;
        float2 w = tw[p];
        float2 u = sa[sidx(p, q)];
        float2 v = sa[sidx(p + 1024, q)];
        float2 tt = cmul(w, v);
        sa[sidx(p, q)]        = make_float2(u.x + tt.x, u.y + tt.y);
        sa[sidx(p + 1024, q)] = make_float2(u.x - tt.x, u.y - tt.y);
    }
    __syncthreads();

    // unpack Re + residual add: sum[s][dout] = x[s][dout] + D*Re(...)
    const float* xb = x + (long)b * S_ * D_;
    float* fp = sum + (long)b * S_ * D_;
    for (int i = tid; i < S_ * 8; i += 512) {
        int s   = i >> 3;
        int col = i & 7;
        int q   = col >> 1;
        int ns  = (S_ - s) & (S_ - 1);
        float2 zs = sa[sidx(s, q)];
        float2 zn = sa[sidx(ns, q)];
        float val = (col & 1) ? (zs.y + zn.y) : (zs.x + zn.x);
        val *= 512.0f;                          // D * 0.5
        int dout = (D_ - (c0 + col)) & (D_ - 1);
        long off = (long)s * D_ + dout;
        fp[off] = val + xb[off];
    }
}

// ===========================================================================
// Kernel 2: t = LN(sum)*g + b  -> fp16  (single fp32 input, float4 I/O)
// ===========================================================================
__device__ __forceinline__ float block_sum_256(float val, float* sh) {
    #pragma unroll
    for (int o = 16; o > 0; o >>= 1) val += __shfl_xor_sync(0xFFFFFFFFu, val, o);
    int lane = threadIdx.x & 31, w = threadIdx.x >> 5;
    if (lane == 0) sh[w] = val;
    __syncthreads();
    if (w == 0) {
        float v = (lane < 8) ? sh[lane] : 0.0f;
        #pragma unroll
        for (int o = 4; o > 0; o >>= 1) v += __shfl_xor_sync(0xFFFFFFFFu, v, o);
        if (lane == 0) sh[0] = v;
    }
    __syncthreads();
    float r = sh[0];
    __syncthreads();
    return r;
}

__global__ __launch_bounds__(256) void add_ln_kernel(
    const float* __restrict__ s_in,
    const float* __restrict__ gamma, const float* __restrict__ beta,
    __half* __restrict__ t_out)
{
    __shared__ float sh[8];
    const int row = blockIdx.x;
    const int tid = threadIdx.x;
    const long base = (long)row * D_ + tid * 4;

    float4 xv = *(const float4*)(s_in + base);
    float v0 = xv.x, v1 = xv.y, v2 = xv.z, v3 = xv.w;

    float mu = block_sum_256(v0 + v1 + v2 + v3, sh) * (1.0f / D_);
    float d0 = v0 - mu, d1 = v1 - mu, d2 = v2 - mu, d3 = v3 - mu;
    float var = block_sum_256(d0 * d0 + d1 * d1 + d2 * d2 + d3 * d3, sh) * (1.0f / D_);
    float rs  = rsqrtf(var + 1e-5f);

    float4 gv = *(const float4*)(gamma + tid * 4);
    float4 bv = *(const float4*)(beta + tid * 4);
    float r0 = d0 * rs * gv.x + bv.x;
    float r1 = d1 * rs * gv.y + bv.y;
    float r2 = d2 * rs * gv.z + bv.z;
    float r3 = d3 * rs * gv.w + bv.w;

    __half2 h01 = __floats2half2_rn(r0, r1);
    __half2 h23 = __floats2half2_rn(r2, r3);
    uint2 pk = make_uint2(*(uint32_t*)&h01, *(uint32_t*)&h23);
    *(uint2*)(t_out + base) = pk;
}

// ===========================================================================
// Kernel 3/4: 1-term fp16 GEMM via mma.sync. Tile 128M x 128N x 32K,
// 128 threads (4 warps, 2x2 grid, warp tile 64x64), cp.async double buffer.
// fuse 0: bias+GELU -> fp16.   fuse 1: bias, *mask -> fp32.   [R10-proven]
// ===========================================================================
#define BK 32
#define ROWB 80                        // 64B data + 16B pad
#define TILE_R_B (128 * ROWB)          // 10240 per 128-row tile
#define OFF_A 0
#define OFF_BW TILE_R_B
#define STAGE_B (2 * TILE_R_B)              // 20480
#define GEMM_SMEM (2 * STAGE_B)             // 40960

__global__ __launch_bounds__(128) void gemm_mma_kernel(
    const __half* __restrict__ A, const __half* __restrict__ Bw,
    const float* __restrict__ bias, const float* __restrict__ mask,
    __half* __restrict__ Ch, float* __restrict__ Cf, int fuse)
{
    extern __shared__ char sm[];
    const uint32_t sb  = smem_u32(sm);
    const int tid  = threadIdx.x;
    const int wid  = tid >> 5;
    const int lane = tid & 31;
    const int bm = blockIdx.y * 128;
    const int bn = blockIdx.x * 128;
    const int warp_m = wid & 1;        // 64-row slab
    const int warp_n = wid >> 1;       // 64-col slab

    auto load_stage = [&](int stage, int k0) {
        const uint32_t st = sb + stage * STAGE_B;
        #pragma unroll
        for (int t = 0; t < 4; t++) {   // A: 512 chunks, 4 per thread
            int idx = tid + t * 128;
            int row = idx >> 2, ch = idx & 3;
            uint32_t so = row * ROWB + ch * 16;
            long ga = (long)(bm + row) * D_ + k0 + ch * 8;
            cp16(st + OFF_A + so, A + ga);
        }
        #pragma unroll
        for (int t = 0; t < 4; t++) {   // W: 512 chunks, 4 per thread
            int idx = tid + t * 128;
            int row = idx >> 2, ch = idx & 3;
            uint32_t so = row * ROWB + ch * 16;
            long gb = (long)(bn + row) * D_ + k0 + ch * 8;
            cp16(st + OFF_BW + so, Bw + gb);
        }
    };

    float acc[4][8][4];
    #pragma unroll
    for (int m = 0; m < 4; m++)
        #pragma unroll
        for (int n = 0; n < 8; n++)
            #pragma unroll
            for (int q = 0; q < 4; q++) acc[m][n][q] = 0.0f;

    load_stage(0, 0);
    CP_COMMIT();

    const int a_lrow = lane & 15;
    const int a_kch  = lane >> 4;
    const int b_lrow = ((lane >> 4) & 1) * 8 + (lane & 7);
    const int b_kch  = (lane >> 3) & 1;

    const int NIT = D_ / BK;   // 32
    for (int it = 0; it < NIT; it++) {
        const int s = it & 1;
        if (it + 1 < NIT) {
            load_stage(s ^ 1, (it + 1) * BK);
            CP_COMMIT();
            CP_WAIT(1);
        } else {
            CP_WAIT(0);
        }
        __syncthreads();

        const uint32_t tA  = sb + s * STAGE_B + OFF_A;
        const uint32_t tBw = sb + s * STAGE_B + OFF_BW;

        #pragma unroll
        for (int ks = 0; ks < 2; ks++) {
            const int kb = ks * 32;
            uint32_t ah[4][4];
            #pragma unroll
            for (int m = 0; m < 4; m++) {
                uint32_t off = (uint32_t)((warp_m * 64 + m * 16 + a_lrow) * ROWB
                                          + kb + a_kch * 16);
                ldsm_x4(ah[m], tA + off);
            }
            #pragma unroll
            for (int p = 0; p < 4; p++) {
                uint32_t off = (uint32_t)((warp_n * 64 + p * 16 + b_lrow) * ROWB
                                          + kb + b_kch * 16);
                uint32_t rh[4];
                ldsm_x4(rh, tBw + off);
                #pragma unroll
                for (int m = 0; m < 4; m++) {
                    mma_f16(acc[m][2 * p],     ah[m], rh);
                    mma_f16(acc[m][2 * p + 1], ah[m], rh + 2);
                }
            }
        }
        __syncthreads();
    }

    // ------------------------------ epilogue -------------------------------
    const int g  = lane >> 2;
    const int t2 = (lane & 3) * 2;
    #pragma unroll
    for (int m = 0; m < 4; m++) {
        const int row0 = bm + warp_m * 64 + m * 16 + g;
        #pragma unroll
        for (int half = 0; half < 2; half++) {
            const int row = row0 + half * 8;
            const float mk = (fuse == 1) ? mask[row] : 0.0f;
            #pragma unroll
            for (int n = 0; n < 8; n++) {
                const int col = bn + warp_n * 64 + n * 8 + t2;
                float v0 = acc[m][n][2 * half]     + bias[col];
                float v1 = acc[m][n][2 * half + 1] + bias[col + 1];
                if (fuse == 0) {
                    v0 = 0.5f * v0 * (1.0f + erff(v0 * 0.70710678118654752f));
                    v1 = 0.5f * v1 * (1.0f + erff(v1 * 0.70710678118654752f));
                    __half h0 = __float2half(v0);
                    __half h1 = __float2half(v1);
                    uint32_t hp = ((uint32_t)__half_as_ushort(h1) << 16)
                                | __half_as_ushort(h0);
                    *(uint32_t*)(Ch + (long)row * D_ + col) = hp;
                } else {
                    float2 o = make_float2(v0 * mk, v1 * mk);
                    *(float2*)(Cf + (long)row * D_ + col) = o;
                }
            }
        }
    }
}

// ===========================================================================
// Launch
// ===========================================================================
extern "C" void kernel_launch(void* const* d_in, const int* in_sizes, int n_in,
                              void* d_out, int out_size)
{
    const float* x    = (const float*)d_in[0];
    const float* mask = (const float*)d_in[1];
    const float* ln_g = (const float*)d_in[2];
    const float* ln_b = (const float*)d_in[3];
    const float* w1   = (const float*)d_in[4];
    const float* b1   = (const float*)d_in[5];
    const float* w2   = (const float*)d_in[6];
    const float* b2   = (const float*)d_in[7];
    float* out = (float*)d_out;

    float *sum; float2 *tw;
    __half *t, *h, *w1h, *w2h;
    cudaGetSymbolAddress((void**)&sum, g_sum);
    cudaGetSymbolAddress((void**)&tw,  g_tw);
    cudaGetSymbolAddress((void**)&t,   g_t);
    cudaGetSymbolAddress((void**)&h,   g_h);
    cudaGetSymbolAddress((void**)&w1h, g_w1h);
    cudaGetSymbolAddress((void**)&w2h, g_w2h);

    cudaFuncSetAttribute(fftc_kernel, cudaFuncAttributeMaxDynamicSharedMemorySize, FFT_SMEM_BYTES);
    cudaFuncSetAttribute(gemm_mma_kernel, cudaFuncAttributeMaxDynamicSharedMemorySize, GEMM_SMEM);

    twinit_kernel<<<4, 256>>>(tw);
    wsplit_kernel<<<dim3(32, 32, 2), dim3(32, 8)>>>(w1, w1h, w2, w2h);
    fftc_kernel<<<dim3(D_ / 8, B_), 512, FFT_SMEM_BYTES>>>(x, sum, tw);
    add_ln_kernel<<<ROWS, 256>>>(sum, ln_g, ln_b, t);
    gemm_mma_kernel<<<dim3(D_ / 128, ROWS / 128), 128, GEMM_SMEM>>>(
        t, w1h, b1, nullptr, h, nullptr, 0);
    gemm_mma_kernel<<<dim3(D_ / 128, ROWS / 128), 128, GEMM_SMEM>>>(
        h, w2h, b2, mask, nullptr, out, 1);
}